// round 5
// baseline (speedup 1.0000x reference)
#include <cuda_runtime.h>
#include <math.h>

#define N_NODES 50000
#define N_EDGES 800000
#define F 128
#define N_GRAPHS 64

// -------- scratch (no allocation allowed) --------
__device__ float g_deg[N_NODES];
__device__ float g_dinv[N_NODES];
__device__ float g_xw[(size_t)N_NODES * F];
__device__ float g_h1[(size_t)N_NODES * F];
__device__ float g_h2[(size_t)N_NODES * F];
__device__ float g_sums[N_GRAPHS * F];
__device__ float g_cnts[N_GRAPHS];
__device__ int   g_src[N_EDGES];
__device__ int   g_dst[N_EDGES];
__device__ int   g_batch[N_NODES];
__device__ int   g_is64;

__device__ __forceinline__ float sigmoidf_(float x) {
    return 1.0f / (1.0f + __expf(-x));
}

// ------------- index dtype detect + normalize to int32 -------------
// If edge_index is int64, every 8-byte word is < N_NODES. If int32, the high
// 32 bits of an 8-byte word hold the next index (nonzero w.h.p.).
__global__ void k_detect(const void* __restrict__ ei) {
    const unsigned long long* p = (const unsigned long long*)ei;
    int is64 = 1;
    for (int i = 0; i < 8; i++)
        if (p[i] >= (unsigned long long)N_NODES) is64 = 0;
    g_is64 = is64;
}

__global__ void k_convert_edges(const void* __restrict__ ei) {
    int e = blockIdx.x * blockDim.x + threadIdx.x;
    if (e >= N_EDGES) return;
    if (g_is64) {
        const long long* p = (const long long*)ei;
        g_src[e] = (int)p[e];
        g_dst[e] = (int)p[e + N_EDGES];
    } else {
        const int* p = (const int*)ei;
        g_src[e] = p[e];
        g_dst[e] = p[e + N_EDGES];
    }
}

__global__ void k_convert_batch(const void* __restrict__ b) {
    int i = blockIdx.x * blockDim.x + threadIdx.x;
    if (i >= N_NODES) return;
    if (g_is64) g_batch[i] = (int)((const long long*)b)[i];
    else        g_batch[i] = ((const int*)b)[i];
}

// ---------------- degree ----------------
__global__ void k_deg_init() {
    int i = blockIdx.x * blockDim.x + threadIdx.x;
    if (i < N_NODES) g_deg[i] = 1.0f;  // self-loop
    if (i < N_GRAPHS * F) g_sums[i] = 0.0f;
    if (i < N_GRAPHS) g_cnts[i] = 0.0f;
}

__global__ void k_deg_accum() {
    int e = blockIdx.x * blockDim.x + threadIdx.x;
    if (e < N_EDGES) atomicAdd(&g_deg[g_dst[e]], 1.0f);
}

__global__ void k_dinv() {
    int i = blockIdx.x * blockDim.x + threadIdx.x;
    if (i < N_NODES) g_dinv[i] = rsqrtf(g_deg[i]);  // deg >= 1 always
}

// ---------------- GEMM: g_xw[n,128] = act(X)[n,128] @ W[128,128] -------------
#define GEMM_ROWS 16
template <int SRC_H1>  // 0: X = external ptr, identity. 1: X = g_h1, sigmoid.
__global__ void k_gemm(const float* __restrict__ Xext, const float* __restrict__ W) {
    __shared__ float xs[GEMM_ROWS][F];
    const float* X = SRC_H1 ? g_h1 : Xext;
    int j = threadIdx.x;                 // 0..127
    int r0 = blockIdx.x * GEMM_ROWS;
#pragma unroll
    for (int r = 0; r < GEMM_ROWS; r++) {
        int row = r0 + r;
        float v = (row < N_NODES) ? X[(size_t)row * F + j] : 0.0f;
        if (SRC_H1) v = sigmoidf_(v);
        xs[r][j] = v;
    }
    __syncthreads();

    float acc[GEMM_ROWS];
#pragma unroll
    for (int r = 0; r < GEMM_ROWS; r++) acc[r] = 0.0f;

#pragma unroll 4
    for (int k = 0; k < F; k++) {
        float wk = W[k * F + j];
#pragma unroll
        for (int r = 0; r < GEMM_ROWS; r++) acc[r] += xs[r][k] * wk;
    }
#pragma unroll
    for (int r = 0; r < GEMM_ROWS; r++) {
        int row = r0 + r;
        if (row < N_NODES) g_xw[(size_t)row * F + j] = acc[r];
    }
}

// --------- out init: h = bias + xw * dinv^2  (self-loop message fused) -------
template <int DST_H2>  // 0: write g_h1, 1: write g_h2
__global__ void k_init_out(const float* __restrict__ bias) {
    int t = blockIdx.x * blockDim.x + threadIdx.x;  // one float4 per thread
    if (t >= N_NODES * (F / 4)) return;
    int i = t >> 5;          // node
    int c4 = t & 31;         // float4 index within row
    float d = g_dinv[i];
    float n2 = d * d;
    float4 v = reinterpret_cast<const float4*>(g_xw)[t];
    const float4 b = reinterpret_cast<const float4*>(bias)[c4];
    float4 o;
    o.x = b.x + v.x * n2;
    o.y = b.y + v.y * n2;
    o.z = b.z + v.z * n2;
    o.w = b.w + v.w * n2;
    float* OUT = DST_H2 ? g_h2 : g_h1;
    reinterpret_cast<float4*>(OUT)[t] = o;
}

// ---------------- edge scatter: one warp per edge ----------------
template <int DST_H2>
__global__ void k_scatter() {
    int warp = (blockIdx.x * blockDim.x + threadIdx.x) >> 5;
    int lane = threadIdx.x & 31;
    if (warp >= N_EDGES) return;
    int s = g_src[warp];
    int d = g_dst[warp];
    float nrm = g_dinv[s] * g_dinv[d];
    float4 v = reinterpret_cast<const float4*>(g_xw + (size_t)s * F)[lane];
    float* OUT = DST_H2 ? g_h2 : g_h1;
    float* o = OUT + (size_t)d * F + lane * 4;
    atomicAdd(o + 0, v.x * nrm);
    atomicAdd(o + 1, v.y * nrm);
    atomicAdd(o + 2, v.z * nrm);
    atomicAdd(o + 3, v.w * nrm);
}

// --------- pool: relu + segment sums, one warp per node (reads g_h2) ---------
__global__ void k_pool() {
    int warp = (blockIdx.x * blockDim.x + threadIdx.x) >> 5;
    int lane = threadIdx.x & 31;
    if (warp >= N_NODES) return;
    int g = g_batch[warp];
    float4 v = reinterpret_cast<const float4*>(g_h2 + (size_t)warp * F)[lane];
    float* s = g_sums + g * F + lane * 4;
    atomicAdd(s + 0, fmaxf(v.x, 0.0f));
    atomicAdd(s + 1, fmaxf(v.y, 0.0f));
    atomicAdd(s + 2, fmaxf(v.z, 0.0f));
    atomicAdd(s + 3, fmaxf(v.w, 0.0f));
    if (lane == 0) atomicAdd(&g_cnts[g], 1.0f);
}

// ---------------- MLP head: one block, thread g handles graph g --------------
__global__ void k_mlp(const float* __restrict__ ilW, const float* __restrict__ ilb,
                      const float* __restrict__ hW, const float* __restrict__ hb,
                      const float* __restrict__ oW, const float* __restrict__ ob,
                      float* __restrict__ out) {
    __shared__ float W1s[F * 64];     // 32 KB
    __shared__ float W2s[64 * 16];
    __shared__ float W3s[16];
    __shared__ float b1s[64], b2s[16];
    int t = threadIdx.x;
    for (int i = t; i < F * 64; i += blockDim.x) W1s[i] = ilW[i];
    for (int i = t; i < 64 * 16; i += blockDim.x) W2s[i] = hW[i];
    if (t < 16) { W3s[t] = oW[t]; b2s[t] = hb[t]; }
    if (t < 64) b1s[t] = ilb[t];
    __syncthreads();

    if (t >= N_GRAPHS) return;
    float inv = 1.0f / fmaxf(g_cnts[t], 1.0f);

    float a1[64];
#pragma unroll
    for (int j = 0; j < 64; j++) a1[j] = b1s[j];
    for (int f = 0; f < F; f++) {
        float p = g_sums[t * F + f] * inv;
#pragma unroll
        for (int j = 0; j < 64; j++) a1[j] += p * W1s[f * 64 + j];
    }
#pragma unroll
    for (int j = 0; j < 64; j++) a1[j] = sigmoidf_(a1[j]);

    float a2[16];
#pragma unroll
    for (int j = 0; j < 16; j++) a2[j] = b2s[j];
    for (int f = 0; f < 64; f++) {
#pragma unroll
        for (int j = 0; j < 16; j++) a2[j] += a1[f] * W2s[f * 16 + j];
    }
    float r = ob[0];
#pragma unroll
    for (int j = 0; j < 16; j++) r += fmaxf(a2[j], 0.0f) * W3s[j];
    out[t] = r;
}

extern "C" void kernel_launch(void* const* d_in, const int* in_sizes, int n_in,
                              void* d_out, int out_size) {
    const float* x    = (const float*)d_in[0];
    const float* W1   = (const float*)d_in[1];
    const float* b1   = (const float*)d_in[2];
    const float* W2   = (const float*)d_in[3];
    const float* b2   = (const float*)d_in[4];
    const float* ilW  = (const float*)d_in[5];
    const float* ilb  = (const float*)d_in[6];
    const float* hW   = (const float*)d_in[7];
    const float* hb   = (const float*)d_in[8];
    const float* oW   = (const float*)d_in[9];
    const float* ob   = (const float*)d_in[10];
    const void*  ei    = d_in[11];
    const void*  batch = d_in[12];
    float* out = (float*)d_out;

    // normalize indices to int32 (handles int32 or int64 inputs)
    k_detect<<<1, 1>>>(ei);
    k_convert_edges<<<(N_EDGES + 255) / 256, 256>>>(ei);
    k_convert_batch<<<(N_NODES + 255) / 256, 256>>>(batch);

    // degrees + norm
    k_deg_init<<<(N_NODES + 255) / 256, 256>>>();
    k_deg_accum<<<(N_EDGES + 255) / 256, 256>>>();
    k_dinv<<<(N_NODES + 255) / 256, 256>>>();

    const int gemm_grid = (N_NODES + GEMM_ROWS - 1) / GEMM_ROWS;
    const int init_grid = (N_NODES * (F / 4) + 255) / 256;
    const int scat_grid = (N_EDGES * 32 + 255) / 256;

    // conv1
    k_gemm<0><<<gemm_grid, 128>>>(x, W1);
    k_init_out<0><<<init_grid, 256>>>(b1);
    k_scatter<0><<<scat_grid, 256>>>();

    // conv2 (sigmoid fused into GEMM input)
    k_gemm<1><<<gemm_grid, 128>>>(nullptr, W2);
    k_init_out<1><<<init_grid, 256>>>(b2);
    k_scatter<1><<<scat_grid, 256>>>();

    // pool (relu fused) + MLP head
    k_pool<<<(N_NODES * 32 + 255) / 256, 256>>>();
    k_mlp<<<1, 256>>>(ilW, ilb, hW, hb, oW, ob, out);
}

// round 6
// speedup vs baseline: 2.4816x; 2.4816x over previous
#include <cuda_runtime.h>
#include <math.h>

#define N_NODES 50000
#define N_EDGES 800000
#define F 128
#define N_GRAPHS 64
#define SCAN_BS 256
#define SCAN_NB ((N_NODES + SCAN_BS - 1) / SCAN_BS)

// -------- scratch (no allocation allowed) --------
__device__ float g_dinv[N_NODES];
__device__ float g_xw[(size_t)N_NODES * F];
__device__ float g_h1[(size_t)N_NODES * F];
__device__ float g_h2[(size_t)N_NODES * F];
__device__ float g_sums[N_GRAPHS * F];
__device__ int   g_cnts[N_GRAPHS];
__device__ int   g_src[N_EDGES];
__device__ int   g_dst[N_EDGES];
__device__ int   g_csrc[N_EDGES];      // CSR: src per slot, sorted by dst
__device__ int   g_ideg[N_NODES];      // in-degree (no self-loop)
__device__ int   g_rowptr[N_NODES + 1];
__device__ int   g_cursor[N_NODES];
__device__ int   g_bsum[SCAN_NB];
__device__ int   g_boff[SCAN_NB];
__device__ int   g_batchv[N_NODES];
__device__ int   g_is64;

__device__ __forceinline__ float sigmoidf_(float x) {
    return 1.0f / (1.0f + __expf(-x));
}

// ---------------- index normalize (int32 or int64 inputs) ----------------
__global__ void k_zero_ideg() {
    int i = blockIdx.x * blockDim.x + threadIdx.x;
    if (i < N_NODES) g_ideg[i] = 0;
}

__global__ void k_detect(const void* __restrict__ ei) {
    const unsigned long long* p = (const unsigned long long*)ei;
    int is64 = 1;
    for (int i = 0; i < 8; i++)
        if (p[i] >= (unsigned long long)N_NODES) is64 = 0;
    g_is64 = is64;
}

// convert + degree histogram fused
__global__ void k_convert_edges(const void* __restrict__ ei) {
    int e = blockIdx.x * blockDim.x + threadIdx.x;
    if (e >= N_EDGES) return;
    int s, d;
    if (g_is64) {
        const long long* p = (const long long*)ei;
        s = (int)p[e];
        d = (int)p[e + N_EDGES];
    } else {
        const int* p = (const int*)ei;
        s = p[e];
        d = p[e + N_EDGES];
    }
    g_src[e] = s;
    g_dst[e] = d;
    atomicAdd(&g_ideg[d], 1);
}

__global__ void k_convert_batch(const void* __restrict__ b) {
    int i = blockIdx.x * blockDim.x + threadIdx.x;
    if (i >= N_NODES) return;
    if (g_is64) g_batchv[i] = (int)((const long long*)b)[i];
    else        g_batchv[i] = ((const int*)b)[i];
}

// ---------------- exclusive scan of g_ideg -> g_rowptr ----------------
__global__ void k_scan1() {   // per-block sums
    __shared__ int sm[SCAN_BS];
    int t = threadIdx.x;
    int i = blockIdx.x * SCAN_BS + t;
    sm[t] = (i < N_NODES) ? g_ideg[i] : 0;
    __syncthreads();
    for (int off = SCAN_BS / 2; off > 0; off >>= 1) {
        if (t < off) sm[t] += sm[t + off];
        __syncthreads();
    }
    if (t == 0) g_bsum[blockIdx.x] = sm[0];
}

__global__ void k_scan2() {   // sequential exclusive scan of block sums (196)
    if (threadIdx.x == 0) {
        int acc = 0;
        for (int b = 0; b < SCAN_NB; b++) {
            g_boff[b] = acc;
            acc += g_bsum[b];
        }
    }
}

__global__ void k_scan3() {   // intra-block exclusive scan + offset
    __shared__ int sm[SCAN_BS];
    int t = threadIdx.x;
    int i = blockIdx.x * SCAN_BS + t;
    int v = (i < N_NODES) ? g_ideg[i] : 0;
    sm[t] = v;
    __syncthreads();
    for (int off = 1; off < SCAN_BS; off <<= 1) {
        int x = (t >= off) ? sm[t - off] : 0;
        __syncthreads();
        sm[t] += x;
        __syncthreads();
    }
    int excl = sm[t] - v + g_boff[blockIdx.x];
    if (i < N_NODES) {
        g_rowptr[i] = excl;
        g_cursor[i] = excl;
        g_dinv[i] = rsqrtf(1.0f + (float)g_ideg[i]);   // self-loop included
    }
    if (i == 0) g_rowptr[N_NODES] = N_EDGES;
}

__global__ void k_fill() {
    int e = blockIdx.x * blockDim.x + threadIdx.x;
    if (e >= N_EDGES) return;
    int d = g_dst[e];
    int pos = atomicAdd(&g_cursor[d], 1);
    g_csrc[pos] = g_src[e];
}

// ---------------- GEMM: g_xw[n,128] = act(X)[n,128] @ W[128,128] -------------
#define GEMM_ROWS 16
template <int SRC_H1>  // 0: X = external ptr, identity. 1: X = g_h1, sigmoid.
__global__ void k_gemm(const float* __restrict__ Xext, const float* __restrict__ W) {
    __shared__ float xs[GEMM_ROWS][F];
    const float* X = SRC_H1 ? g_h1 : Xext;
    int j = threadIdx.x;                 // 0..127
    int r0 = blockIdx.x * GEMM_ROWS;
#pragma unroll
    for (int r = 0; r < GEMM_ROWS; r++) {
        int row = r0 + r;
        float v = (row < N_NODES) ? X[(size_t)row * F + j] : 0.0f;
        if (SRC_H1) v = sigmoidf_(v);
        xs[r][j] = v;
    }
    __syncthreads();

    float acc[GEMM_ROWS];
#pragma unroll
    for (int r = 0; r < GEMM_ROWS; r++) acc[r] = 0.0f;

#pragma unroll 4
    for (int k = 0; k < F; k++) {
        float wk = W[k * F + j];
#pragma unroll
        for (int r = 0; r < GEMM_ROWS; r++) acc[r] += xs[r][k] * wk;
    }
#pragma unroll
    for (int r = 0; r < GEMM_ROWS; r++) {
        int row = r0 + r;
        if (row < N_NODES) g_xw[(size_t)row * F + j] = acc[r];
    }
}

// ------------- gather: one warp per node, atomic-free aggregation -------------
// acc = bias + xw[d]*dinv[d]^2 + sum_e xw[src_e] * dinv[src_e]*dinv[d]
template <int DST_H2>
__global__ void k_gather(const float* __restrict__ bias) {
    int node = (blockIdx.x * blockDim.x + threadIdx.x) >> 5;
    int lane = threadIdx.x & 31;
    if (node >= N_NODES) return;
    float dd = g_dinv[node];
    float4 xv = reinterpret_cast<const float4*>(g_xw + (size_t)node * F)[lane];
    float4 bb = reinterpret_cast<const float4*>(bias)[lane];
    float n2 = dd * dd;
    float4 acc;
    acc.x = bb.x + xv.x * n2;
    acc.y = bb.y + xv.y * n2;
    acc.z = bb.z + xv.z * n2;
    acc.w = bb.w + xv.w * n2;

    int beg = g_rowptr[node];
    int end = g_rowptr[node + 1];
    for (int e = beg; e < end; e++) {
        int s = g_csrc[e];                       // broadcast load
        float nrm = g_dinv[s] * dd;              // broadcast load
        float4 v = reinterpret_cast<const float4*>(g_xw + (size_t)s * F)[lane];
        acc.x += v.x * nrm;
        acc.y += v.y * nrm;
        acc.z += v.z * nrm;
        acc.w += v.w * nrm;
    }
    float* OUT = DST_H2 ? g_h2 : g_h1;
    reinterpret_cast<float4*>(OUT + (size_t)node * F)[lane] = acc;
}

// ------- pool: batch is sorted -> block g owns a contiguous node range -------
__global__ void k_pool_seg() {
    int g = blockIdx.x;
    int t = threadIdx.x;   // 0..127, one feature column each

    // lower_bound(g) and lower_bound(g+1) over sorted g_batchv
    int lo = 0, hi = N_NODES;
    while (lo < hi) { int m = (lo + hi) >> 1; if (g_batchv[m] < g) lo = m + 1; else hi = m; }
    int start = lo;
    lo = start; hi = N_NODES;
    while (lo < hi) { int m = (lo + hi) >> 1; if (g_batchv[m] < g + 1) lo = m + 1; else hi = m; }
    int stop = lo;

    float acc = 0.0f;
    for (int n = start; n < stop; n++)
        acc += fmaxf(g_h2[(size_t)n * F + t], 0.0f);
    g_sums[g * F + t] = acc;
    if (t == 0) g_cnts[g] = stop - start;
}

// ---------------- MLP head: one block, thread g handles graph g --------------
__global__ void k_mlp(const float* __restrict__ ilW, const float* __restrict__ ilb,
                      const float* __restrict__ hW, const float* __restrict__ hb,
                      const float* __restrict__ oW, const float* __restrict__ ob,
                      float* __restrict__ out) {
    __shared__ float W1s[F * 64];     // 32 KB
    __shared__ float W2s[64 * 16];
    __shared__ float W3s[16];
    __shared__ float b1s[64], b2s[16];
    int t = threadIdx.x;
    for (int i = t; i < F * 64; i += blockDim.x) W1s[i] = ilW[i];
    for (int i = t; i < 64 * 16; i += blockDim.x) W2s[i] = hW[i];
    if (t < 16) { W3s[t] = oW[t]; b2s[t] = hb[t]; }
    if (t < 64) b1s[t] = ilb[t];
    __syncthreads();

    if (t >= N_GRAPHS) return;
    float inv = 1.0f / fmaxf((float)g_cnts[t], 1.0f);

    float a1[64];
#pragma unroll
    for (int j = 0; j < 64; j++) a1[j] = b1s[j];
    for (int f = 0; f < F; f++) {
        float p = g_sums[t * F + f] * inv;
#pragma unroll
        for (int j = 0; j < 64; j++) a1[j] += p * W1s[f * 64 + j];
    }
#pragma unroll
    for (int j = 0; j < 64; j++) a1[j] = sigmoidf_(a1[j]);

    float a2[16];
#pragma unroll
    for (int j = 0; j < 16; j++) a2[j] = b2s[j];
    for (int f = 0; f < 64; f++) {
#pragma unroll
        for (int j = 0; j < 16; j++) a2[j] += a1[f] * W2s[f * 16 + j];
    }
    float r = ob[0];
#pragma unroll
    for (int j = 0; j < 16; j++) r += fmaxf(a2[j], 0.0f) * W3s[j];
    out[t] = r;
}

extern "C" void kernel_launch(void* const* d_in, const int* in_sizes, int n_in,
                              void* d_out, int out_size) {
    const float* x    = (const float*)d_in[0];
    const float* W1   = (const float*)d_in[1];
    const float* b1   = (const float*)d_in[2];
    const float* W2   = (const float*)d_in[3];
    const float* b2   = (const float*)d_in[4];
    const float* ilW  = (const float*)d_in[5];
    const float* ilb  = (const float*)d_in[6];
    const float* hW   = (const float*)d_in[7];
    const float* hb   = (const float*)d_in[8];
    const float* oW   = (const float*)d_in[9];
    const float* ob   = (const float*)d_in[10];
    const void*  ei    = d_in[11];
    const void*  batch = d_in[12];
    float* out = (float*)d_out;

    // index normalize + CSR build
    k_zero_ideg<<<SCAN_NB, SCAN_BS>>>();
    k_detect<<<1, 1>>>(ei);
    k_convert_edges<<<(N_EDGES + 255) / 256, 256>>>(ei);
    k_convert_batch<<<(N_NODES + 255) / 256, 256>>>(batch);
    k_scan1<<<SCAN_NB, SCAN_BS>>>();
    k_scan2<<<1, 32>>>();
    k_scan3<<<SCAN_NB, SCAN_BS>>>();
    k_fill<<<(N_EDGES + 255) / 256, 256>>>();

    const int gemm_grid = (N_NODES + GEMM_ROWS - 1) / GEMM_ROWS;
    const int gath_grid = (N_NODES * 32 + 255) / 256;

    // conv1
    k_gemm<0><<<gemm_grid, 128>>>(x, W1);
    k_gather<0><<<gath_grid, 256>>>(b1);

    // conv2 (sigmoid fused into GEMM input)
    k_gemm<1><<<gemm_grid, 128>>>(nullptr, W2);
    k_gather<1><<<gath_grid, 256>>>(b2);

    // pool (relu fused, segmented — batch sorted) + MLP head
    k_pool_seg<<<N_GRAPHS, F>>>();
    k_mlp<<<1, 256>>>(ilW, ilb, hW, hb, oW, ob, out);
}